// round 2
// baseline (speedup 1.0000x reference)
#include <cuda_runtime.h>
#include <math.h>

// Problem constants
#define BB    2
#define SS    1024
#define DD    1024
#define NH    16
#define HD    64
#define NL    12
#define DFF   4096
#define RH    128
#define VOC   32000
#define MM    (BB*SS)          // 2048 tokens
#define BHT   (BB*NH)          // 32 batch-heads

typedef unsigned long long ull;

// packed fp32x2 FMA (Blackwell FFMA2) — two IEEE fp32 FMAs per instruction
static __device__ __forceinline__ void fma2(ull &acc, ull a, ull b) {
    asm("fma.rn.f32x2 %0, %1, %2, %0;" : "+l"(acc) : "l"(a), "l"(b));
}
static __device__ __forceinline__ float lo32(ull v) { return __uint_as_float((unsigned)v); }
static __device__ __forceinline__ float hi32(ull v) { return __uint_as_float((unsigned)(v >> 32)); }

// ---------------- static device scratch (no allocations allowed) ----------------
__device__ float g_h [MM*DD];
__device__ float g_h1[MM*DD];
__device__ float g_t [MM*DD];
__device__ float g_q [MM*DD];
__device__ float g_k [MM*DD];
__device__ float g_v [MM*DD];
__device__ float g_a [MM*DD];
__device__ float g_ht[MM*DD];
__device__ float g_f1[MM*DFF];
__device__ float g_zr[MM*RH];
__device__ float g_sc[(size_t)BHT*SS*SS];   // 128 MB attention scores
__device__ unsigned char g_skip[MM];
__device__ int g_cnt[3];

// ---------------- init / counters ----------------
__global__ void zero_cnt_kernel() {
    if (threadIdx.x < 3) g_cnt[threadIdx.x] = 0;
}

// ---------------- embedding + positional encoding ----------------
__global__ __launch_bounds__(256) void embed_kernel(const int* __restrict__ x,
                                                    const float* __restrict__ emb) {
    int tok = blockIdx.x;
    int s = tok % SS;
    int id = x[tok];
    int d0 = threadIdx.x * 4;
    float4 ev = *(const float4*)(emb + (size_t)id * DD + d0);
    float o[4] = {ev.x, ev.y, ev.z, ev.w};
#pragma unroll
    for (int j = 0; j < 4; j++) {
        int d = d0 + j;
        float ang = (float)s * expf((float)(d & ~1) * (-9.210340371976184f / 1024.0f));
        float pe = (d & 1) ? cosf(ang) : sinf(ang);
        o[j] = o[j] * 32.0f + pe;   // sqrt(1024)=32
    }
    *(float4*)(g_h + (size_t)tok * DD + d0) = make_float4(o[0], o[1], o[2], o[3]);
}

// ---------------- tiled SGEMM (FFMA2): C = [res +] A(MxK)@B(KxN) [+bias] [relu] -----
// Tiles: 128(M) x 128(N) x 16(K). 256 threads, each computes 8x8.
// Accumulators packed along M (pairs); B duplicated in smem so (b,b) pairs load directly.
// Requires M%128==0, N%128==0, K%16==0.
__global__ __launch_bounds__(256, 2) void sgemm_kernel(const float* __restrict__ A,
                                                       const float* __restrict__ B,
                                                       const float* __restrict__ bias,
                                                       const float* __restrict__ res,
                                                       float* __restrict__ C,
                                                       int M, int N, int K, int relu) {
    __shared__ float Ast[16][128];   // [k][m]
    __shared__ float Bsd[16][256];   // [k][2n] duplicated: Bsd[k][2n]=Bsd[k][2n+1]=B[k][n]
    int tid = threadIdx.x;
    int bm = blockIdx.y * 128, bn = blockIdx.x * 128;
    int tx = tid & 15, ty = tid >> 4;
    int m0 = ty * 8, n0 = tx * 8;

    ull acc[4][8];
#pragma unroll
    for (int i = 0; i < 4; i++)
#pragma unroll
        for (int j = 0; j < 8; j++) acc[i][j] = 0ULL;

    for (int kb = 0; kb < K; kb += 16) {
        // A fill: 128 rows x 16 k = 512 float4, 2 per thread (transposed store)
#pragma unroll
        for (int p = 0; p < 2; p++) {
            int idx = tid * 2 + p;
            int row = idx >> 2;
            int kc = (idx & 3) * 4;
            float4 av = *(const float4*)(A + (size_t)(bm + row) * K + kb + kc);
            Ast[kc + 0][row] = av.x;
            Ast[kc + 1][row] = av.y;
            Ast[kc + 2][row] = av.z;
            Ast[kc + 3][row] = av.w;
        }
        // B fill with duplication: 16 k x 128 n = 512 float4 src, 2 per thread
#pragma unroll
        for (int p = 0; p < 2; p++) {
            int idx = tid * 2 + p;
            int bkr = idx >> 5;
            int bc4 = (idx & 31) * 4;
            float4 bv = *(const float4*)(B + (size_t)(kb + bkr) * N + bn + bc4);
            *(float4*)&Bsd[bkr][2 * bc4 + 0] = make_float4(bv.x, bv.x, bv.y, bv.y);
            *(float4*)&Bsd[bkr][2 * bc4 + 4] = make_float4(bv.z, bv.z, bv.w, bv.w);
        }
        __syncthreads();
#pragma unroll
        for (int k = 0; k < 16; k++) {
            // A pairs: (m0+0,m0+1),(m0+2,m0+3),(m0+4,m0+5),(m0+6,m0+7)
            const ull* ap = (const ull*)&Ast[k][m0];
            ull a0 = ap[0], a1 = ap[1], a2 = ap[2], a3 = ap[3];
            // B dup pairs for n0..n0+7
            const ull* bp = (const ull*)&Bsd[k][2 * n0];
            ull b[8];
#pragma unroll
            for (int j = 0; j < 8; j++) b[j] = bp[j];
#pragma unroll
            for (int j = 0; j < 8; j++) {
                fma2(acc[0][j], a0, b[j]);
                fma2(acc[1][j], a1, b[j]);
                fma2(acc[2][j], a2, b[j]);
                fma2(acc[3][j], a3, b[j]);
            }
        }
        __syncthreads();
    }
#pragma unroll
    for (int mp = 0; mp < 4; mp++) {
        int m = bm + m0 + 2 * mp;
#pragma unroll
        for (int j = 0; j < 8; j++) {
            int n = bn + n0 + j;
            float v0 = lo32(acc[mp][j]);
            float v1 = hi32(acc[mp][j]);
            if (bias) { float bv = bias[n]; v0 += bv; v1 += bv; }
            if (res)  { v0 += res[(size_t)m * N + n]; v1 += res[(size_t)(m + 1) * N + n]; }
            if (relu) { v0 = fmaxf(v0, 0.f); v1 = fmaxf(v1, 0.f); }
            C[(size_t)m * N + n] = v0;
            C[(size_t)(m + 1) * N + n] = v1;
        }
    }
}

// ---------------- attention: scores = Q Kt / 8 with causal mask (FFMA2) ----------
__global__ __launch_bounds__(256) void attn_scores_kernel() {
    int kt = blockIdx.x, qt = blockIdx.y, bh = blockIdx.z;
    int b = bh >> 4, hh = bh & 15;
    int tid = threadIdx.x;
    float* sc = g_sc + ((size_t)bh * SS + qt * 64) * SS + kt * 64;
    if (kt > qt) {  // fully masked tile
        for (int i = tid; i < 64 * 64; i += 256)
            sc[(size_t)(i >> 6) * SS + (i & 63)] = -1e30f;
        return;
    }
    __shared__ float Qs[64][66];
    __shared__ float Ks[64][66];
    const float* qb = g_q + ((size_t)(b * SS + qt * 64)) * DD + hh * HD;
    const float* kb = g_k + ((size_t)(b * SS + kt * 64)) * DD + hh * HD;
    for (int i = tid; i < 64 * 64; i += 256) {
        int r = i >> 6, c = i & 63;
        Qs[r][c] = qb[(size_t)r * DD + c];
        Ks[r][c] = kb[(size_t)r * DD + c];
    }
    __syncthreads();
    int tx = tid & 15, ty = tid >> 4;
    int q0 = ty * 4, k0 = tx * 4;
    ull acc[4][4];
#pragma unroll
    for (int i = 0; i < 4; i++)
#pragma unroll
        for (int j = 0; j < 4; j++) acc[i][j] = 0ULL;
#pragma unroll 4
    for (int e2 = 0; e2 < 32; e2++) {
        ull qv[4], kv[4];
#pragma unroll
        for (int i = 0; i < 4; i++) qv[i] = *(const ull*)&Qs[q0 + i][2 * e2];
#pragma unroll
        for (int j = 0; j < 4; j++) kv[j] = *(const ull*)&Ks[k0 + j][2 * e2];
#pragma unroll
        for (int i = 0; i < 4; i++)
#pragma unroll
            for (int j = 0; j < 4; j++) fma2(acc[i][j], qv[i], kv[j]);
    }
    bool diag = (kt == qt);
#pragma unroll
    for (int i = 0; i < 4; i++) {
        int qq = qt * 64 + q0 + i;
#pragma unroll
        for (int j = 0; j < 4; j++) {
            int kk = kt * 64 + k0 + j;
            float v = (lo32(acc[i][j]) + hi32(acc[i][j])) * 0.125f;
            if (diag && kk > qq) v = -1e30f;
            sc[(size_t)(q0 + i) * SS + (k0 + j)] = v;
        }
    }
}

// ---------------- row softmax over S (masked entries are -1e30) ----------------
__global__ __launch_bounds__(256) void softmax_kernel() {
    size_t row = blockIdx.x;
    float* sc = g_sc + row * SS;
    int tid = threadIdx.x;
    float4 v = *(float4*)&sc[tid * 4];
    __shared__ float red[8];
    __shared__ float stat;
    float m = fmaxf(fmaxf(v.x, v.y), fmaxf(v.z, v.w));
    for (int o = 16; o; o >>= 1) m = fmaxf(m, __shfl_down_sync(~0u, m, o));
    if ((tid & 31) == 0) red[tid >> 5] = m;
    __syncthreads();
    if (tid == 0) {
        float t = red[0];
        for (int i = 1; i < 8; i++) t = fmaxf(t, red[i]);
        stat = t;
    }
    __syncthreads();
    float mx = stat;
    float e0 = expf(v.x - mx), e1 = expf(v.y - mx), e2 = expf(v.z - mx), e3 = expf(v.w - mx);
    float s = e0 + e1 + e2 + e3;
    for (int o = 16; o; o >>= 1) s += __shfl_down_sync(~0u, s, o);
    __syncthreads();
    if ((tid & 31) == 0) red[tid >> 5] = s;
    __syncthreads();
    if (tid == 0) {
        float t = 0.f;
        for (int i = 0; i < 8; i++) t += red[i];
        stat = t;
    }
    __syncthreads();
    float inv = 1.0f / stat;
    *(float4*)&sc[tid * 4] = make_float4(e0 * inv, e1 * inv, e2 * inv, e3 * inv);
}

// ---------------- attention: A = P @ V (FFMA2, V transposed in smem) -------------
__global__ __launch_bounds__(256) void attn_av_kernel() {
    int qt = blockIdx.x, bh = blockIdx.y;
    int b = bh >> 4, hh = bh & 15;
    int tid = threadIdx.x;
    __shared__ float Ps[64][66];
    __shared__ float Vt[64][66];   // Vt[e][kk]
    int tx = tid & 15, ty = tid >> 4;
    int q0 = ty * 4, e0 = tx * 4;
    ull acc[4][4];
#pragma unroll
    for (int i = 0; i < 4; i++)
#pragma unroll
        for (int j = 0; j < 4; j++) acc[i][j] = 0ULL;
    const float* scb = g_sc + ((size_t)bh * SS + qt * 64) * SS;
    for (int kt = 0; kt <= qt; kt++) {
        const float* vb = g_v + ((size_t)(b * SS + kt * 64)) * DD + hh * HD;
        for (int i = tid; i < 64 * 64; i += 256) {
            int r = i >> 6, c = i & 63;
            Ps[r][c] = scb[(size_t)r * SS + kt * 64 + c];
            Vt[c][r] = vb[(size_t)r * DD + c];
        }
        __syncthreads();
#pragma unroll 4
        for (int k2 = 0; k2 < 32; k2++) {
            ull pv[4], vv[4];
#pragma unroll
            for (int i = 0; i < 4; i++) pv[i] = *(const ull*)&Ps[q0 + i][2 * k2];
#pragma unroll
            for (int j = 0; j < 4; j++) vv[j] = *(const ull*)&Vt[e0 + j][2 * k2];
#pragma unroll
            for (int i = 0; i < 4; i++)
#pragma unroll
                for (int j = 0; j < 4; j++) fma2(acc[i][j], pv[i], vv[j]);
        }
        __syncthreads();
    }
#pragma unroll
    for (int i = 0; i < 4; i++)
#pragma unroll
        for (int j = 0; j < 4; j++)
            g_a[((size_t)(b * SS + qt * 64 + q0 + i)) * DD + hh * HD + e0 + j] =
                lo32(acc[i][j]) + hi32(acc[i][j]);
}

// ---------------- LayerNorm (row = 1024) ----------------
__global__ __launch_bounds__(256) void ln_kernel(const float* __restrict__ in,
                                                 const float* __restrict__ g,
                                                 const float* __restrict__ bsh,
                                                 float* __restrict__ out) {
    size_t row = blockIdx.x;
    const float* x = in + row * DD;
    int tid = threadIdx.x;
    float4 v = *(const float4*)&x[tid * 4];
    __shared__ float red[8];
    __shared__ float stat;
    float s = v.x + v.y + v.z + v.w;
    for (int o = 16; o; o >>= 1) s += __shfl_down_sync(~0u, s, o);
    if ((tid & 31) == 0) red[tid >> 5] = s;
    __syncthreads();
    if (tid == 0) {
        float t = 0.f;
        for (int i = 0; i < 8; i++) t += red[i];
        stat = t * (1.0f / DD);
    }
    __syncthreads();
    float mu = stat;
    float dx = v.x - mu, dy = v.y - mu, dz = v.z - mu, dw = v.w - mu;
    float ss = dx * dx + dy * dy + dz * dz + dw * dw;
    for (int o = 16; o; o >>= 1) ss += __shfl_down_sync(~0u, ss, o);
    __syncthreads();
    if ((tid & 31) == 0) red[tid >> 5] = ss;
    __syncthreads();
    if (tid == 0) {
        float t = 0.f;
        for (int i = 0; i < 8; i++) t += red[i];
        stat = rsqrtf(t * (1.0f / DD) + 1e-5f);
    }
    __syncthreads();
    float rs = stat;
    float4 gg = *(const float4*)&g[tid * 4];
    float4 bb = *(const float4*)&bsh[tid * 4];
    float4 o4 = make_float4(dx * rs * gg.x + bb.x, dy * rs * gg.y + bb.y,
                            dz * rs * gg.z + bb.z, dw * rs * gg.w + bb.w);
    *(float4*)&out[row * DD + tid * 4] = o4;
}

// ---------------- router head: rlog = zr @ rW2 + rb2 ; argmax ; counters ------
__global__ __launch_bounds__(256) void router2_kernel(const float* __restrict__ rw2,
                                                      const float* __restrict__ rb2) {
    int w = (blockIdx.x * blockDim.x + threadIdx.x) >> 5;
    int lane = threadIdx.x & 31;
    if (w >= MM) return;
    const float* z = g_zr + (size_t)w * RH;
    float s0 = 0.f, s1 = 0.f, s2 = 0.f;
#pragma unroll
    for (int u = 0; u < 4; u++) {
        int j = lane + 32 * u;
        float zv = z[j];
        s0 += zv * rw2[j * 3 + 0];
        s1 += zv * rw2[j * 3 + 1];
        s2 += zv * rw2[j * 3 + 2];
    }
    for (int o = 16; o; o >>= 1) {
        s0 += __shfl_down_sync(~0u, s0, o);
        s1 += __shfl_down_sync(~0u, s1, o);
        s2 += __shfl_down_sync(~0u, s2, o);
    }
    if (lane == 0) {
        s0 += rb2[0]; s1 += rb2[1]; s2 += rb2[2];
        int a = 0; float best = s0;
        if (s1 > best) { best = s1; a = 1; }
        if (s2 > best) { best = s2; a = 2; }
        g_skip[w] = (a == 0);
        atomicAdd(&g_cnt[a], 1);
    }
}

// ---------------- per-token merge: h = skip ? h : ht ----------------
__global__ __launch_bounds__(256) void merge_kernel() {
    int tok = blockIdx.x;
    if (g_skip[tok]) return;
    int tid = threadIdx.x;
    ((float4*)g_h)[(size_t)tok * 256 + tid] = ((float4*)g_ht)[(size_t)tok * 256 + tid];
}

// ---------------- final scalar stats ----------------
__global__ void scalars_kernel(float* out) {
    float fs = (float)g_cnt[0], ff = (float)g_cnt[1], fr = (float)g_cnt[2];
    out[(size_t)MM * VOC + 0] = (ff + fr) / (float)MM;             // effective depth
    out[(size_t)MM * VOC + 1] = fs / (float)(MM * NL);             // skip frac
    out[(size_t)MM * VOC + 2] = ff / (float)(MM * NL);             // fwd frac
    out[(size_t)MM * VOC + 3] = fr / (float)(MM * NL);             // rec frac
}

// ======================= host launch =======================
extern "C" void kernel_launch(void* const* d_in, const int* in_sizes, int n_in,
                              void* d_out, int out_size) {
    const int*   x     = (const int*)d_in[0];
    const float* emb   = (const float*)d_in[1];
    const float* Wq    = (const float*)d_in[2];
    const float* bq    = (const float*)d_in[3];
    const float* Wk    = (const float*)d_in[4];
    const float* bk    = (const float*)d_in[5];
    const float* Wv    = (const float*)d_in[6];
    const float* bv    = (const float*)d_in[7];
    const float* Wo    = (const float*)d_in[8];
    const float* bo    = (const float*)d_in[9];
    const float* ln1g  = (const float*)d_in[10];
    const float* ln1b  = (const float*)d_in[11];
    const float* Wf1   = (const float*)d_in[12];
    const float* bf1   = (const float*)d_in[13];
    const float* Wf2   = (const float*)d_in[14];
    const float* bf2   = (const float*)d_in[15];
    const float* ln2g  = (const float*)d_in[16];
    const float* ln2b  = (const float*)d_in[17];
    const float* rW1   = (const float*)d_in[18];
    const float* rb1   = (const float*)d_in[19];
    const float* rW2   = (const float*)d_in[20];
    const float* rb2   = (const float*)d_in[21];
    const float* Wout  = (const float*)d_in[22];
    const float* bout  = (const float*)d_in[23];
    float* out = (float*)d_out;

    float *h, *h1, *t, *q, *k, *v, *a, *ht, *f1, *zr;
    cudaGetSymbolAddress((void**)&h,  g_h);
    cudaGetSymbolAddress((void**)&h1, g_h1);
    cudaGetSymbolAddress((void**)&t,  g_t);
    cudaGetSymbolAddress((void**)&q,  g_q);
    cudaGetSymbolAddress((void**)&k,  g_k);
    cudaGetSymbolAddress((void**)&v,  g_v);
    cudaGetSymbolAddress((void**)&a,  g_a);
    cudaGetSymbolAddress((void**)&ht, g_ht);
    cudaGetSymbolAddress((void**)&f1, g_f1);
    cudaGetSymbolAddress((void**)&zr, g_zr);

    zero_cnt_kernel<<<1, 32>>>();
    embed_kernel<<<MM, 256>>>(x, emb);

    for (int l = 0; l < NL; l++) {
        // router
        sgemm_kernel<<<dim3(RH / 128, MM / 128), 256>>>(
            h, rW1 + (size_t)l * DD * RH, rb1 + l * RH, nullptr, zr, MM, RH, DD, 1);
        router2_kernel<<<MM / 8, 256>>>(rW2 + (size_t)l * RH * 3, rb2 + l * 3);
        // QKV
        sgemm_kernel<<<dim3(DD / 128, MM / 128), 256>>>(h, Wq, bq, nullptr, q, MM, DD, DD, 0);
        sgemm_kernel<<<dim3(DD / 128, MM / 128), 256>>>(h, Wk, bk, nullptr, k, MM, DD, DD, 0);
        sgemm_kernel<<<dim3(DD / 128, MM / 128), 256>>>(h, Wv, bv, nullptr, v, MM, DD, DD, 0);
        // attention
        attn_scores_kernel<<<dim3(SS / 64, SS / 64, BHT), 256>>>();
        softmax_kernel<<<BHT * SS, 256>>>();
        attn_av_kernel<<<dim3(SS / 64, BHT), 256>>>();
        // O-proj + residual, LN1
        sgemm_kernel<<<dim3(DD / 128, MM / 128), 256>>>(a, Wo, bo, h, t, MM, DD, DD, 0);
        ln_kernel<<<MM, 256>>>(t, ln1g, ln1b, h1);
        // FFN + residual, LN2
        sgemm_kernel<<<dim3(DFF / 128, MM / 128), 256>>>(h1, Wf1, bf1, nullptr, f1, MM, DFF, DD, 1);
        sgemm_kernel<<<dim3(DD / 128, MM / 128), 256>>>(f1, Wf2, bf2, h1, t, MM, DD, DFF, 0);
        ln_kernel<<<MM, 256>>>(t, ln2g, ln2b, ht);
        // per-token skip merge
        merge_kernel<<<MM, 256>>>();
    }

    // logits
    sgemm_kernel<<<dim3(VOC / 128, MM / 128), 256>>>(h, Wout, bout, nullptr, out, MM, VOC, DD, 0);
    scalars_kernel<<<1, 1>>>(out);
}